// round 15
// baseline (speedup 1.0000x reference)
#include <cuda_runtime.h>
#include <cuda_fp16.h>
#include <math.h>

#define BB   2
#define SS   2048
#define DD   2048
#define HQ   16
#define HKV  4
#define HD   128
#define KVD  512
#define MM   (BB*SS)
#define NT   (SS/64)

// Scratch (device globals) — fp16 operands, fp32 I/O
__device__ __half g_Q[(size_t)MM * DD];
__device__ __half g_K[(size_t)MM * KVD];
__device__ __half g_V[(size_t)MM * KVD];
__device__ __half g_Vt[(size_t)BB * KVD * SS];
__device__ __half g_H[(size_t)MM * DD];
__device__ __half g_Wq[(size_t)DD * DD];    // [n][k2] h2, k-pairs permuted
__device__ __half g_Wk[(size_t)DD * KVD];   // [n][k2] h2
__device__ __half g_Wv[(size_t)DD * KVD];   // [n][k2] h2

__device__ __forceinline__ unsigned h2pack(float lo, float hi) {
    __half2 h = __floats2half2_rn(lo, hi);
    return *reinterpret_cast<unsigned*>(&h);
}

__device__ __forceinline__ void mma_f16(float c[4], const unsigned a[4], const unsigned b[2]) {
    asm volatile(
        "mma.sync.aligned.m16n8k16.row.col.f32.f16.f16.f32 "
        "{%0,%1,%2,%3},{%4,%5,%6,%7},{%8,%9},{%0,%1,%2,%3};"
        : "+f"(c[0]), "+f"(c[1]), "+f"(c[2]), "+f"(c[3])
        : "r"(a[0]), "r"(a[1]), "r"(a[2]), "r"(a[3]), "r"(b[0]), "r"(b[1]));
}

#define CP16(dst, src) \
    asm volatile("cp.async.cg.shared.global [%0], [%1], 16;" :: "r"(dst), "l"(src))
#define CPCOMMIT() asm volatile("cp.async.commit_group;")
#define CPWAIT(N)  asm volatile("cp.async.wait_group %0;" :: "n"(N))

#define MBAR_INIT(addr, cnt) \
    asm volatile("mbarrier.init.shared.b64 [%0], %1;" :: "r"(addr), "r"(cnt) : "memory")
#define MBAR_ARRIVE(addr) \
    asm volatile("mbarrier.arrive.shared.b64 _, [%0];" :: "r"(addr) : "memory")
#define CPASYNC_MBAR_ARRIVE(addr) \
    asm volatile("cp.async.mbarrier.arrive.noinc.shared.b64 [%0];" :: "r"(addr) : "memory")

#define MBAR_WAIT(addr, par) do { \
    unsigned _m = (addr), _p = (par), _d; \
    asm volatile("{\n\t.reg .pred p;\n\t" \
        "mbarrier.try_wait.parity.acquire.cta.shared::cta.b64 p, [%1], %2;\n\t" \
        "selp.b32 %0, 1, 0, p;\n\t}" : "=r"(_d) : "r"(_m), "r"(_p) : "memory"); \
    if (!_d) { \
        asm volatile("{\n\t.reg .pred P1;\n\t" \
            "WL%=:\n\t" \
            "mbarrier.try_wait.parity.acquire.cta.shared::cta.b64 P1, [%0], %1, 0x989680;\n\t" \
            "@P1 bra.uni WD%=;\n\t" \
            "bra.uni WL%=;\n\t" \
            "WD%=:\n\t}" :: "r"(_m), "r"(_p) : "memory"); \
    } \
} while (0)

// ---------------------------------------------------------------------------
// H: fp32 -> fp16, pairs permuted [P0,P4,P1,P5,P2,P6,P3,P7] per 16-value group.
// ---------------------------------------------------------------------------
__global__ void cvt_h(__half* __restrict__ dst, const float* __restrict__ src, int n16)
{
    int i = blockIdx.x * blockDim.x + threadIdx.x;
    const int stride = gridDim.x * blockDim.x;
    for (; i < n16; i += stride) {
        const float4* s = (const float4*)src + 4 * (size_t)i;
        float4 s0 = s[0], s1 = s[1], s2 = s[2], s3 = s[3];
        uint4 o0, o1;
        o0.x = h2pack(s0.x, s0.y);
        o0.y = h2pack(s2.x, s2.y);
        o0.z = h2pack(s0.z, s0.w);
        o0.w = h2pack(s2.z, s2.w);
        o1.x = h2pack(s1.x, s1.y);
        o1.y = h2pack(s3.x, s3.y);
        o1.z = h2pack(s1.z, s1.w);
        o1.w = h2pack(s3.z, s3.w);
        uint4* o = (uint4*)dst + 2 * (size_t)i;
        o[0] = o0;
        o[1] = o1;
    }
}

// ---------------------------------------------------------------------------
// W [k=2048][N] fp32 -> Wt h2 [N][k2=1024], k-pairs permuted per 16-k group.
// Tile 64k x 32n; block (32,8). zsel picks (dst,src) pair for the fused launch.
// ---------------------------------------------------------------------------
__device__ __forceinline__ void cvt_wt_body(
    __half* __restrict__ dst, const float* __restrict__ src, int N)
{
    __shared__ float t[64][33];
    const int k0 = blockIdx.y * 64, n0 = blockIdx.x * 32;
    #pragma unroll
    for (int i = 0; i < 8; i++) {
        int row = threadIdx.y + i * 8;
        t[row][threadIdx.x] = src[(size_t)(k0 + row) * N + n0 + threadIdx.x];
    }
    __syncthreads();
    const int x = threadIdx.x;               // output k2 slot 0..31
    const int grp = x >> 3, q = x & 7;
    const int lp = (q & 1) ? (q >> 1) + 4 : (q >> 1);
    const int lk = 2 * (grp * 8 + lp);       // local source k (0..62)
    unsigned* d2 = (unsigned*)dst;
    #pragma unroll
    for (int i = 0; i < 4; i++) {
        int n = threadIdx.y + i * 8;
        d2[(size_t)(n0 + n) * (DD / 2) + (k0 >> 1) + x] =
            h2pack(t[lk][n], t[lk + 1][n]);
    }
}

__global__ void cvt_wt(__half* __restrict__ dst, const float* __restrict__ src, int N)
{
    cvt_wt_body(dst, src, N);
}

__global__ void cvt_wt_kv(
    __half* __restrict__ dk, const float* __restrict__ sk,
    __half* __restrict__ dv, const float* __restrict__ sv)
{
    if (blockIdx.z == 0) cvt_wt_body(dk, sk, KVD);
    else                 cvt_wt_body(dv, sv, KVD);
}

// ---------------------------------------------------------------------------
// V half [b][s][gd] -> Vt h2 [b*512+gd][s/2], s pairs permuted per 16-s group.
// ---------------------------------------------------------------------------
__global__ void transpose_v(__half* __restrict__ Vt, const __half* __restrict__ V)
{
    __shared__ __half t[64][36];
    const int s0 = blockIdx.x * 64, gd0 = blockIdx.y * 32, b = blockIdx.z;
    #pragma unroll
    for (int i = 0; i < 8; i++) {
        int e = (threadIdx.y + i * 8) * 32 + threadIdx.x;
        int srow = e >> 5, gcol = e & 31;
        t[srow][gcol] = V[((size_t)b * SS + s0 + srow) * KVD + gd0 + gcol];
    }
    __syncthreads();
    const int x = threadIdx.x;
    const int grp = x >> 3, qq = x & 7;
    const int lp = (qq & 1) ? (qq >> 1) + 4 : (qq >> 1);
    const int sl = grp * 16 + 2 * lp;
    unsigned* Vt2 = (unsigned*)Vt;
    #pragma unroll
    for (int i = 0; i < 4; i++) {
        int gd = threadIdx.y + i * 8;
        float lo = __half2float(t[sl][gd]);
        float hi = __half2float(t[sl + 1][gd]);
        Vt2[((size_t)b * KVD + gd0 + gd) * (SS / 2) + (s0 >> 1) + x] = h2pack(lo, hi);
    }
}

// ---------------------------------------------------------------------------
// fp16 GEMM + bias: 8 warps (2m x 4n), CTA 128x256x32, 3-stage cp.async,
// one __syncthreads per K-iter. A: [m][k2] stride 24; B: Wt [n][k2] stride 24
// (pair-permuted) -> all fragment loads are LDS.64.
// ---------------------------------------------------------------------------
#define GA 3072
#define GB 6144
#define GSTG (GA + GB)
#define GEMM_SMEM_BYTES (GSTG * 3 * 4)

__device__ __forceinline__ void gemm_stage(
    unsigned sA, unsigned sB, const __half* __restrict__ X, const unsigned* __restrict__ Wt2,
    int bm, int bn, int k0, int tid)
{
    #pragma unroll
    for (int it = 0; it < 2; it++) {          // A: 128 rows x 4 chunks
        int f = tid + it * 256;
        int m  = f >> 2;
        int ch = f & 3;
        CP16(sA + (m * 24 + 4 * ch) * 4, X + (size_t)(bm + m) * DD + k0 + ch * 8);
    }
    const int k02 = k0 >> 1;
    #pragma unroll
    for (int it = 0; it < 4; it++) {          // B: 256 n-rows x 4 chunks
        int f = tid + it * 256;
        int row = f >> 2;
        int ch  = f & 3;
        CP16(sB + (row * 24 + 4 * ch) * 4,
             Wt2 + (size_t)(bn + row) * (DD / 2) + k02 + 4 * ch);
    }
}

__global__ __launch_bounds__(256) void gemm_f16(
    const __half* __restrict__ X,
    const __half* __restrict__ Wq, const float* __restrict__ bq, __half* __restrict__ Yq,
    const __half* __restrict__ Wk, const float* __restrict__ bk, __half* __restrict__ Yk,
    const __half* __restrict__ Wv, const float* __restrict__ bv, __half* __restrict__ Yv,
    float qscale, int zoff)
{
    const int z = blockIdx.z + zoff;
    const __half* __restrict__ W  = (z == 0) ? Wq : (z == 1) ? Wk : Wv;
    const float*  __restrict__ bi = (z == 0) ? bq : (z == 1) ? bk : bv;
    __half*       __restrict__ Y  = (z == 0) ? Yq : (z == 1) ? Yk : Yv;
    const int   N      = (z == 0) ? DD : KVD;
    const float oscale = (z == 0) ? qscale : 1.0f;
    const int   permv  = (z == 2) ? 0 : 1;

    extern __shared__ unsigned smg[];
    const int tid  = threadIdx.x;
    const int lane = tid & 31;
    const int wid  = tid >> 5;
    const int wm   = wid >> 2;
    const int wn   = wid & 3;
    const int lr   = lane >> 2;
    const int lc   = lane & 3;
    const int bm = blockIdx.y * 128;
    const int bn = blockIdx.x * 256;

    unsigned sbase = (unsigned)__cvta_generic_to_shared(smg);

    float acc[4][8][4];
    #pragma unroll
    for (int i = 0; i < 4; i++)
        #pragma unroll
        for (int j = 0; j < 8; j++)
            #pragma unroll
            for (int k = 0; k < 4; k++) acc[i][j][k] = 0.f;

    const int nK = DD / 32;
    gemm_stage(sbase, sbase + GA * 4, X, (const unsigned*)W, bm, bn, 0, tid);
    CPCOMMIT();
    gemm_stage(sbase + GSTG * 4, sbase + (GSTG + GA) * 4,
               X, (const unsigned*)W, bm, bn, 32, tid);
    CPCOMMIT();

    for (int i = 0; i < nK; i++) {
        if (i + 1 < nK) { CPWAIT(1); } else { CPWAIT(0); }
        __syncthreads();
        if (i + 2 < nK) {
            unsigned boff = ((i + 2) % 3) * GSTG * 4;
            gemm_stage(sbase + boff, sbase + boff + GA * 4,
                       X, (const unsigned*)W, bm, bn, (i + 2) * 32, tid);
            CPCOMMIT();
        }
        const unsigned* As = smg + (i % 3) * GSTG;
        const unsigned* Bs = As + GA;

        #pragma unroll
        for (int g = 0; g < 2; g++) {
            unsigned af[4][4], bf[8][2];
            #pragma unroll
            for (int mt = 0; mt < 4; mt++) {
                int r = wm * 64 + mt * 16 + lr;
                uint2 u1 = *(const uint2*)&As[r * 24 + 8 * g + 2 * lc];
                uint2 u2 = *(const uint2*)&As[(r + 8) * 24 + 8 * g + 2 * lc];
                af[mt][0] = u1.x; af[mt][1] = u2.x;
                af[mt][2] = u1.y; af[mt][3] = u2.y;
            }
            #pragma unroll
            for (int nt = 0; nt < 8; nt++) {
                int n = wn * 64 + nt * 8 + lr;
                uint2 bu = *(const uint2*)&Bs[n * 24 + 8 * g + 2 * lc];
                bf[nt][0] = bu.x;
                bf[nt][1] = bu.y;
            }
            #pragma unroll
            for (int mt = 0; mt < 4; mt++)
                #pragma unroll
                for (int nt = 0; nt < 8; nt++)
                    mma_f16(acc[mt][nt], af[mt], bf[nt]);
        }
    }

    #pragma unroll
    for (int mt = 0; mt < 4; mt++) {
        int r = bm + wm * 64 + mt * 16 + lr;
        #pragma unroll
        for (int nt = 0; nt < 8; nt++) {
            int base = bn + wn * 64 + nt * 8;
            int c0 = base + 2 * lc;
            float bv0 = bi[c0], bv1 = bi[c0 + 1];
            unsigned v0 = h2pack((acc[mt][nt][0] + bv0) * oscale,
                                 (acc[mt][nt][1] + bv1) * oscale);
            unsigned v1 = h2pack((acc[mt][nt][2] + bv0) * oscale,
                                 (acc[mt][nt][3] + bv1) * oscale);
            int idx;
            if (permv) {
                int L = (c0 & 15) >> 1;
                int phys = (L < 4) ? 2 * L : 2 * L - 7;
                idx = (c0 & ~15) + 2 * phys;
            } else {
                idx = c0;
            }
            *(unsigned*)(Y + (size_t)r * N + idx) = v0;
            *(unsigned*)(Y + (size_t)(r + 8) * N + idx) = v1;
        }
    }
}

// ---------------------------------------------------------------------------
// fp16 flash attention — byte-identical to round 14 (128-key softmax blocks,
// quad-buffered 64-key slots, no __syncthreads in main loop).
// ---------------------------------------------------------------------------
#define KSLOT 4608
#define VSLOT 5120
#define VBASE 18432
#define BARW  38912
#define ATTN_SMEM_BYTES (38944 * 4)

__global__ __launch_bounds__(256) void attn_f16(
    const __half* __restrict__ Q, const __half* __restrict__ K,
    const __half* __restrict__ Vt, float* __restrict__ O)
{
    extern __shared__ unsigned sm[];

    const int tid  = threadIdx.x;
    const int lane = tid & 31;
    const int wid  = tid >> 5;
    const int lr = lane >> 2;
    const int lc = lane & 3;
    const int r0 = 16 * wid + lr;
    const int q0 = blockIdx.x * 128;
    const int h  = blockIdx.y;
    const int b  = blockIdx.z;
    const int g  = h & (HKV - 1);

    const __half* Qb = Q + (size_t)b * SS * DD  + (size_t)h * HD;
    const __half* Kb = K + (size_t)b * SS * KVD + (size_t)g * HD;
    const unsigned* Vb2 = (const unsigned*)Vt + ((size_t)b * KVD + (size_t)g * HD) * (SS / 2);

    unsigned sbase = (unsigned)__cvta_generic_to_shared(sm);

    if (tid == 0) {
        #pragma unroll
        for (int s = 0; s < 4; s++) {
            MBAR_INIT(sbase + (BARW + 2 * s) * 4, 256);
            MBAR_INIT(sbase + (BARW + 8 + 2 * s) * 4, 256);
        }
    }

    #pragma unroll
    for (int it = 0; it < 8; it++) {
        int f = tid + it * 256;
        int q  = f >> 4;
        int ch = f & 15;
        CP16(sbase + (q * 72 + 4 * ch) * 4, Qb + (size_t)(q0 + q) * DD + ch * 8);
    }
    CPCOMMIT();
    CPWAIT(0);
    __syncthreads();

    unsigned qa[8][4];
    #pragma unroll
    for (int gch = 0; gch < 8; gch++) {
        uint2 u1 = *(const uint2*)&sm[r0 * 72 + 8 * gch + 2 * lc];
        uint2 u2 = *(const uint2*)&sm[(r0 + 8) * 72 + 8 * gch + 2 * lc];
        qa[gch][0] = u1.x; qa[gch][1] = u2.x;
        qa[gch][2] = u1.y; qa[gch][3] = u2.y;
    }
    __syncthreads();

    #pragma unroll
    for (int s = 0; s < 2; s++) {
        unsigned sKs = sbase + s * KSLOT * 4;
        unsigned sVs = sbase + (VBASE + s * VSLOT) * 4;
        #pragma unroll
        for (int it = 0; it < 4; it++) {
            int f = tid + it * 256;
            int key = f >> 4;
            int ch  = f & 15;
            CP16(sKs + (key * 72 + 4 * ch) * 4,
                 Kb + (size_t)(s * 64 + key) * KVD + ch * 8);
        }
        #pragma unroll
        for (int it = 0; it < 4; it++) {
            int f = tid + it * 256;
            int d  = f >> 3;
            int ch = f & 7;
            CP16(sVs + (d * 40 + 4 * ch) * 4,
                 Vb2 + (size_t)d * (SS / 2) + s * 32 + ch * 4);
        }
        CPASYNC_MBAR_ARRIVE(sbase + (BARW + 2 * s) * 4);
    }

    float o[16][4];
    #pragma unroll
    for (int dt = 0; dt < 16; dt++)
        #pragma unroll
        for (int k = 0; k < 4; k++) o[dt][k] = 0.f;
    float rm0 = -INFINITY, rm1 = -INFINITY, rl0 = 0.f, rl1 = 0.f;

    #pragma unroll 1
    for (int j = 0; j < NT / 2; j++) {
        #pragma unroll
        for (int pp = 0; pp < 2; pp++) {
            const int ft = 2 * j + 2 + pp;
            if (ft < NT) {
                const int slot = ft & 3;
                if (ft >= 4) MBAR_WAIT(sbase + (BARW + 8 + 2 * slot) * 4,
                                       (unsigned)(((ft >> 2) - 1) & 1));
                unsigned sKs = sbase + slot * KSLOT * 4;
                unsigned sVs = sbase + (VBASE + slot * VSLOT) * 4;
                #pragma unroll
                for (int it = 0; it < 4; it++) {
                    int f = tid + it * 256;
                    int key = f >> 4;
                    int ch  = f & 15;
                    CP16(sKs + (key * 72 + 4 * ch) * 4,
                         Kb + (size_t)(ft * 64 + key) * KVD + ch * 8);
                }
                #pragma unroll
                for (int it = 0; it < 4; it++) {
                    int f = tid + it * 256;
                    int d  = f >> 3;
                    int ch = f & 7;
                    CP16(sVs + (d * 40 + 4 * ch) * 4,
                         Vb2 + (size_t)d * (SS / 2) + ft * 32 + ch * 4);
                }
                CPASYNC_MBAR_ARRIVE(sbase + (BARW + 2 * slot) * 4);
            }
        }

        const int t0 = 2 * j;
        const int s0 = t0 & 3, s1 = (t0 + 1) & 3;
        const unsigned par = (unsigned)((t0 >> 2) & 1);

        MBAR_WAIT(sbase + (BARW + 2 * s0) * 4, par);
        const unsigned* KstA = sm + s0 * KSLOT;
        float saccA[8][4];
        #pragma unroll
        for (int nt = 0; nt < 8; nt++)
            #pragma unroll
            for (int k = 0; k < 4; k++) saccA[nt][k] = 0.f;
        #pragma unroll
        for (int gch = 0; gch < 8; gch++) {
            #pragma unroll
            for (int nt = 0; nt < 8; nt++) {
                uint2 bu = *(const uint2*)&KstA[(8 * nt + lr) * 72 + 8 * gch + 2 * lc];
                unsigned bf[2] = { bu.x, bu.y };
                mma_f16(saccA[nt], qa[gch], bf);
            }
        }

        MBAR_WAIT(sbase + (BARW + 2 * s1) * 4, par);
        const unsigned* KstB = sm + s1 * KSLOT;
        float saccB[8][4];
        #pragma unroll
        for (int nt = 0; nt < 8; nt++)
            #pragma unroll
            for (int k = 0; k < 4; k++) saccB[nt][k] = 0.f;
        #pragma unroll
        for (int gch = 0; gch < 8; gch++) {
            #pragma unroll
            for (int nt = 0; nt < 8; nt++) {
                uint2 bu = *(const uint2*)&KstB[(8 * nt + lr) * 72 + 8 * gch + 2 * lc];
                unsigned bf[2] = { bu.x, bu.y };
                mma_f16(saccB[nt], qa[gch], bf);
            }
        }

        float m0 = saccA[0][0], m1 = saccA[0][2];
        #pragma unroll
        for (int nt = 0; nt < 8; nt++) {
            m0 = fmaxf(m0, fmaxf(saccA[nt][0], saccA[nt][1]));
            m1 = fmaxf(m1, fmaxf(saccA[nt][2], saccA[nt][3]));
            m0 = fmaxf(m0, fmaxf(saccB[nt][0], saccB[nt][1]));
            m1 = fmaxf(m1, fmaxf(saccB[nt][2], saccB[nt][3]));
        }
        m0 = fmaxf(m0, __shfl_xor_sync(0xffffffffu, m0, 1));
        m0 = fmaxf(m0, __shfl_xor_sync(0xffffffffu, m0, 2));
        m1 = fmaxf(m1, __shfl_xor_sync(0xffffffffu, m1, 1));
        m1 = fmaxf(m1, __shfl_xor_sync(0xffffffffu, m1, 2));
        float mn0 = fmaxf(rm0, m0), mn1 = fmaxf(rm1, m1);
        float al0 = __expf(rm0 - mn0), al1 = __expf(rm1 - mn1);
        float sum0 = 0.f, sum1 = 0.f;
        unsigned paA[4][4], paB[4][4];
        #pragma unroll
        for (int jj = 0; jj < 4; jj++) {
            float e00 = __expf(saccA[2 * jj][0] - mn0);
            float e01 = __expf(saccA[2 * jj][1] - mn0);
            float e02 = __expf(saccA[2 * jj][2] - mn1);
            float e03 = __expf(saccA[2 * jj][3] - mn1);
            float e10 = __expf(saccA[2 * jj + 1][0] - mn0);
            float e11 = __expf(saccA[2 * jj + 1][1] - mn0);
            float e12 = __expf(saccA[2 * jj + 1][2] - mn1);
            float e13 = __expf(saccA[2 * jj + 1][3] - mn1);
            sum0 += e00 + e01 + e10 + e11;
            sum1 += e02 + e03 + e12 + e13;
            paA[jj][0] = h2pack(e00, e01);
            paA[jj][1] = h2pack(e02, e03);
            paA[jj][2] = h2pack(e10, e11);
            paA[jj][3] = h2pack(e12, e13);
        }
        #pragma unroll
        for (int jj = 0; jj < 4; jj++) {
            float e00 = __expf(saccB[2 * jj][0] - mn0);
            float e01 = __expf(saccB[2 * jj][1] - mn0);
            float e02 = __expf(saccB[2 * jj][2] - mn1);
            float e03 = __expf(saccB[2 * jj][3] - mn1);
            float e10 = __expf(saccB[2 * jj + 1][0] - mn0);
            float e11 = __expf(saccB[2 * jj + 1][1] - mn0);
            float e12 = __expf(saccB[2 * jj + 1][2] - mn1);
            float e13 = __expf(saccB[2 * jj + 1][3] - mn1);
            sum0 += e00 + e01 + e10 + e11;
            sum1 += e02 + e03 + e12 + e13;
            paB[jj][0] = h2pack(e00, e01);
            paB[jj][1] = h2pack(e02, e03);
            paB[jj][2] = h2pack(e10, e11);
            paB[jj][3] = h2pack(e12, e13);
        }
        sum0 += __shfl_xor_sync(0xffffffffu, sum0, 1);
        sum0 += __shfl_xor_sync(0xffffffffu, sum0, 2);
        sum1 += __shfl_xor_sync(0xffffffffu, sum1, 1);
        sum1 += __shfl_xor_sync(0xffffffffu, sum1, 2);
        rl0 = rl0 * al0 + sum0;  rm0 = mn0;
        rl1 = rl1 * al1 + sum1;  rm1 = mn1;
        #pragma unroll
        for (int dt = 0; dt < 16; dt++) {
            o[dt][0] *= al0;  o[dt][1] *= al0;
            o[dt][2] *= al1;  o[dt][3] *= al1;
        }

        const unsigned* VtsA = sm + VBASE + s0 * VSLOT;
        #pragma unroll
        for (int jj = 0; jj < 4; jj++) {
            #pragma unroll
            for (int dt = 0; dt < 16; dt++) {
                uint2 vu = *(const uint2*)&VtsA[(8 * dt + lr) * 40 + 8 * jj + 2 * lc];
                unsigned bf[2] = { vu.x, vu.y };
                mma_f16(o[dt], paA[jj], bf);
            }
        }
        MBAR_ARRIVE(sbase + (BARW + 8 + 2 * s0) * 4);

        const unsigned* VtsB = sm + VBASE + s1 * VSLOT;
        #pragma unroll
        for (int jj = 0; jj < 4; jj++) {
            #pragma unroll
            for (int dt = 0; dt < 16; dt++) {
                uint2 vu = *(const uint2*)&VtsB[(8 * dt + lr) * 40 + 8 * jj + 2 * lc];
                unsigned bf[2] = { vu.x, vu.y };
                mma_f16(o[dt], paB[jj], bf);
            }
        }
        MBAR_ARRIVE(sbase + (BARW + 8 + 2 * s1) * 4);
    }

    float* Ob = O + (size_t)b * SS * DD + (size_t)h * HD;
    float inv0 = 1.f / rl0, inv1 = 1.f / rl1;
    #pragma unroll
    for (int dt = 0; dt < 16; dt++) {
        int cc = 8 * dt + 2 * lc;
        *(float2*)(Ob + (size_t)(q0 + r0) * DD + cc) =
            make_float2(o[dt][0] * inv0, o[dt][1] * inv0);
        *(float2*)(Ob + (size_t)(q0 + r0 + 8) * DD + cc) =
            make_float2(o[dt][2] * inv1, o[dt][3] * inv1);
    }
}

// ---------------------------------------------------------------------------
extern "C" void kernel_launch(void* const* d_in, const int* in_sizes, int n_in,
                              void* d_out, int out_size)
{
    (void)in_sizes; (void)n_in; (void)out_size;
    const float* H  = (const float*)d_in[0];
    const float* Wq = (const float*)d_in[1];
    const float* bq = (const float*)d_in[2];
    const float* Wk = (const float*)d_in[3];
    const float* bk = (const float*)d_in[4];
    const float* Wv = (const float*)d_in[5];
    const float* bv = (const float*)d_in[6];
    float* out = (float*)d_out;

    static cudaStream_t s2 = 0;
    static cudaEvent_t eFork = 0, eH = 0, eKV = 0;
    if (s2 == 0) {
        cudaStreamCreateWithFlags(&s2, cudaStreamNonBlocking);
        cudaEventCreateWithFlags(&eFork, cudaEventDisableTiming);
        cudaEventCreateWithFlags(&eH,    cudaEventDisableTiming);
        cudaEventCreateWithFlags(&eKV,   cudaEventDisableTiming);
    }

    __half *Qp, *Kp, *Vp, *Vtp, *Hp, *Wqp, *Wkp, *Wvp;
    cudaGetSymbolAddress((void**)&Qp,  g_Q);
    cudaGetSymbolAddress((void**)&Kp,  g_K);
    cudaGetSymbolAddress((void**)&Vp,  g_V);
    cudaGetSymbolAddress((void**)&Vtp, g_Vt);
    cudaGetSymbolAddress((void**)&Hp,  g_H);
    cudaGetSymbolAddress((void**)&Wqp, g_Wq);
    cudaGetSymbolAddress((void**)&Wkp, g_Wk);
    cudaGetSymbolAddress((void**)&Wvp, g_Wv);

    cudaFuncSetAttribute(gemm_f16,
                         cudaFuncAttributeMaxDynamicSharedMemorySize, GEMM_SMEM_BYTES);
    cudaFuncSetAttribute(attn_f16,
                         cudaFuncAttributeMaxDynamicSharedMemorySize, ATTN_SMEM_BYTES);

    const float scale = 0.08838834764831845f;  // 1/sqrt(128)
    const int nb = 148 * 8;

    cudaEventRecord(eFork, 0);
    cudaStreamWaitEvent(s2, eFork, 0);

    // Stream 0: H cvt (#1), Wq transpose-cvt (#2)
    cvt_h<<<nb, 256>>>(Hp, H, (int)((size_t)MM * DD / 16));
    cvt_wt<<<dim3(DD / 32, DD / 64), dim3(32, 8)>>>(Wqp, Wq, DD);
    cudaEventRecord(eH, 0);

    // Stream s2: fused Wk/Wv transpose-cvt (#3), then wait for H.
    cvt_wt_kv<<<dim3(KVD / 32, DD / 64, 2), dim3(32, 8), 0, s2>>>(Wkp, Wk, Wvp, Wv);
    cudaStreamWaitEvent(s2, eH, 0);

    // Stream 0: Q projection (#4 — profiled next round).
    gemm_f16<<<dim3(DD / 256, MM / 128, 1), 256, GEMM_SMEM_BYTES>>>(
        Hp, Wqp, bq, Qp, Wkp, bk, Kp, Wvp, bv, Vp, scale, 0);

    // Stream s2: K + V projections, then V transpose.
    gemm_f16<<<dim3(KVD / 256, MM / 128, 2), 256, GEMM_SMEM_BYTES, s2>>>(
        Hp, Wqp, bq, Qp, Wkp, bk, Kp, Wvp, bv, Vp, scale, 1);
    transpose_v<<<dim3(SS / 64, KVD / 32, BB), dim3(32, 8), 0, s2>>>(Vtp, Vp);
    cudaEventRecord(eKV, s2);

    cudaStreamWaitEvent(0, eKV, 0);
    attn_f16<<<dim3(SS / 128, HQ, BB), 256, ATTN_SMEM_BYTES>>>(Qp, Kp, Vtp, out);
}

// round 16
// speedup vs baseline: 1.0359x; 1.0359x over previous
#include <cuda_runtime.h>
#include <cuda_fp16.h>
#include <math.h>

#define BB   2
#define SS   2048
#define DD   2048
#define HQ   16
#define HKV  4
#define HD   128
#define KVD  512
#define MM   (BB*SS)
#define NT   (SS/64)

// Scratch (device globals) — fp16 operands, fp32 I/O
__device__ __half g_Q[(size_t)MM * DD];
__device__ __half g_K[(size_t)MM * KVD];
__device__ __half g_V[(size_t)MM * KVD];
__device__ __half g_Vt[(size_t)BB * KVD * SS];
__device__ __half g_H[(size_t)MM * DD];
__device__ __half g_Wq[(size_t)DD * DD];    // h2 [k/2][n]
__device__ __half g_Wk[(size_t)DD * KVD];   // h2 [k/2][n]
__device__ __half g_Wv[(size_t)DD * KVD];   // h2 [k/2][n]

__device__ __forceinline__ unsigned h2pack(float lo, float hi) {
    __half2 h = __floats2half2_rn(lo, hi);
    return *reinterpret_cast<unsigned*>(&h);
}

__device__ __forceinline__ void mma_f16(float c[4], const unsigned a[4], const unsigned b[2]) {
    asm volatile(
        "mma.sync.aligned.m16n8k16.row.col.f32.f16.f16.f32 "
        "{%0,%1,%2,%3},{%4,%5,%6,%7},{%8,%9},{%0,%1,%2,%3};"
        : "+f"(c[0]), "+f"(c[1]), "+f"(c[2]), "+f"(c[3])
        : "r"(a[0]), "r"(a[1]), "r"(a[2]), "r"(a[3]), "r"(b[0]), "r"(b[1]));
}

#define CP16(dst, src) \
    asm volatile("cp.async.cg.shared.global [%0], [%1], 16;" :: "r"(dst), "l"(src))
#define CPCOMMIT() asm volatile("cp.async.commit_group;")
#define CPWAIT(N)  asm volatile("cp.async.wait_group %0;" :: "n"(N))

#define MBAR_INIT(addr, cnt) \
    asm volatile("mbarrier.init.shared.b64 [%0], %1;" :: "r"(addr), "r"(cnt) : "memory")
#define MBAR_ARRIVE(addr) \
    asm volatile("mbarrier.arrive.shared.b64 _, [%0];" :: "r"(addr) : "memory")
#define CPASYNC_MBAR_ARRIVE(addr) \
    asm volatile("cp.async.mbarrier.arrive.noinc.shared.b64 [%0];" :: "r"(addr) : "memory")

#define MBAR_WAIT(addr, par) do { \
    unsigned _m = (addr), _p = (par), _d; \
    asm volatile("{\n\t.reg .pred p;\n\t" \
        "mbarrier.try_wait.parity.acquire.cta.shared::cta.b64 p, [%1], %2;\n\t" \
        "selp.b32 %0, 1, 0, p;\n\t}" : "=r"(_d) : "r"(_m), "r"(_p) : "memory"); \
    if (!_d) { \
        asm volatile("{\n\t.reg .pred P1;\n\t" \
            "WL%=:\n\t" \
            "mbarrier.try_wait.parity.acquire.cta.shared::cta.b64 P1, [%0], %1, 0x989680;\n\t" \
            "@P1 bra.uni WD%=;\n\t" \
            "bra.uni WL%=;\n\t" \
            "WD%=:\n\t}" :: "r"(_m), "r"(_p) : "memory"); \
    } \
} while (0)

// ---------------------------------------------------------------------------
// H: fp32 -> fp16, pairs permuted [P0,P4,P1,P5,P2,P6,P3,P7] per 16-value group.
// ---------------------------------------------------------------------------
__global__ void cvt_h(__half* __restrict__ dst, const float* __restrict__ src, int n16)
{
    int i = blockIdx.x * blockDim.x + threadIdx.x;
    const int stride = gridDim.x * blockDim.x;
    for (; i < n16; i += stride) {
        const float4* s = (const float4*)src + 4 * (size_t)i;
        float4 s0 = s[0], s1 = s[1], s2 = s[2], s3 = s[3];
        uint4 o0, o1;
        o0.x = h2pack(s0.x, s0.y);
        o0.y = h2pack(s2.x, s2.y);
        o0.z = h2pack(s0.z, s0.w);
        o0.w = h2pack(s2.z, s2.w);
        o1.x = h2pack(s1.x, s1.y);
        o1.y = h2pack(s3.x, s3.y);
        o1.z = h2pack(s1.z, s1.w);
        o1.w = h2pack(s3.z, s3.w);
        uint4* o = (uint4*)dst + 2 * (size_t)i;
        o[0] = o0;
        o[1] = o1;
    }
}

// ---------------------------------------------------------------------------
// W: fp32 [k][n] -> h2 [k/2][n]  (streaming, round-14 layout)
// ---------------------------------------------------------------------------
__device__ __forceinline__ void cvt_w_body(
    __half* __restrict__ dst, const float* __restrict__ src, int K2, int N)
{
    int j = blockIdx.x * blockDim.x + threadIdx.x;
    const int stride = gridDim.x * blockDim.x;
    const int nq = N / 4;
    const int total = K2 * nq;
    for (; j < total; j += stride) {
        int i  = j / nq;
        int n4 = (j % nq) * 4;
        float4 a = *(const float4*)(src + (size_t)(2 * i) * N + n4);
        float4 b = *(const float4*)(src + (size_t)(2 * i + 1) * N + n4);
        uint4 o;
        o.x = h2pack(a.x, b.x);
        o.y = h2pack(a.y, b.y);
        o.z = h2pack(a.z, b.z);
        o.w = h2pack(a.w, b.w);
        *((uint4*)dst + (size_t)i * nq + (n4 >> 2)) = o;
    }
}

__global__ void cvt_w(__half* __restrict__ dst, const float* __restrict__ src,
                      int K2, int N)
{
    cvt_w_body(dst, src, K2, N);
}

__global__ void cvt_w_kv(
    __half* __restrict__ dk, const float* __restrict__ sk,
    __half* __restrict__ dv, const float* __restrict__ sv)
{
    if (blockIdx.z == 0) cvt_w_body(dk, sk, DD / 2, KVD);
    else                 cvt_w_body(dv, sv, DD / 2, KVD);
}

// ---------------------------------------------------------------------------
// V half [b][s][gd] -> Vt h2 [b*512+gd][s/2], s pairs permuted per 16-s group.
// ---------------------------------------------------------------------------
__global__ void transpose_v(__half* __restrict__ Vt, const __half* __restrict__ V)
{
    __shared__ __half t[64][36];
    const int s0 = blockIdx.x * 64, gd0 = blockIdx.y * 32, b = blockIdx.z;
    #pragma unroll
    for (int i = 0; i < 8; i++) {
        int e = (threadIdx.y + i * 8) * 32 + threadIdx.x;
        int srow = e >> 5, gcol = e & 31;
        t[srow][gcol] = V[((size_t)b * SS + s0 + srow) * KVD + gd0 + gcol];
    }
    __syncthreads();
    const int x = threadIdx.x;
    const int grp = x >> 3, qq = x & 7;
    const int lp = (qq & 1) ? (qq >> 1) + 4 : (qq >> 1);
    const int sl = grp * 16 + 2 * lp;
    unsigned* Vt2 = (unsigned*)Vt;
    #pragma unroll
    for (int i = 0; i < 4; i++) {
        int gd = threadIdx.y + i * 8;
        float lo = __half2float(t[sl][gd]);
        float hi = __half2float(t[sl + 1][gd]);
        Vt2[((size_t)b * KVD + gd0 + gd) * (SS / 2) + (s0 >> 1) + x] = h2pack(lo, hi);
    }
}

// ---------------------------------------------------------------------------
// fp16 GEMM + bias: CTA tile 128x128x32, 8 warps (2m x 4n), warp tile 64x32
// (acc = 64 regs -> 2 CTAs/SM), 3-stage cp.async, one __syncthreads/K-iter.
// A: [m][k2] stride 24 (LDS.64 a-frags); B: [k2][n] stride 136 (scalar,
// phase-conflict-free). z = blockIdx.z + zoff: 0=Q, 1=K, 2=V.
// ---------------------------------------------------------------------------
#define GA 3072
#define GB 2176
#define GSTG (GA + GB)
#define GEMM_SMEM_BYTES (GSTG * 3 * 4)

__device__ __forceinline__ void gemm_stage(
    unsigned sA, unsigned sB, const __half* __restrict__ X, const unsigned* __restrict__ W2,
    int N, int bm, int bn, int k0, int tid)
{
    #pragma unroll
    for (int it = 0; it < 2; it++) {          // A: 128 rows x 4 chunks
        int f = tid + it * 256;
        int m  = f >> 2;
        int ch = f & 3;
        CP16(sA + (m * 24 + 4 * ch) * 4, X + (size_t)(bm + m) * DD + k0 + ch * 8);
    }
    const int k02 = k0 >> 1;
    #pragma unroll
    for (int it = 0; it < 2; it++) {          // B: 16 k2-rows x 32 chunks
        int f = tid + it * 256;
        int kk2 = f >> 5;
        int nq  = (f & 31) * 4;
        CP16(sB + (kk2 * 136 + nq) * 4, W2 + (size_t)(k02 + kk2) * N + bn + nq);
    }
}

__global__ __launch_bounds__(256, 2) void gemm_f16(
    const __half* __restrict__ X,
    const __half* __restrict__ Wq, const float* __restrict__ bq, __half* __restrict__ Yq,
    const __half* __restrict__ Wk, const float* __restrict__ bk, __half* __restrict__ Yk,
    const __half* __restrict__ Wv, const float* __restrict__ bv, __half* __restrict__ Yv,
    float qscale, int zoff)
{
    const int z = blockIdx.z + zoff;
    const __half* __restrict__ W  = (z == 0) ? Wq : (z == 1) ? Wk : Wv;
    const float*  __restrict__ bi = (z == 0) ? bq : (z == 1) ? bk : bv;
    __half*       __restrict__ Y  = (z == 0) ? Yq : (z == 1) ? Yk : Yv;
    const int   N      = (z == 0) ? DD : KVD;
    const float oscale = (z == 0) ? qscale : 1.0f;
    const int   permv  = (z == 2) ? 0 : 1;

    extern __shared__ unsigned smg[];
    const int tid  = threadIdx.x;
    const int lane = tid & 31;
    const int wid  = tid >> 5;
    const int wm   = wid & 1;      // 0..1 (64-row groups)
    const int wn   = wid >> 1;     // 0..3 (32-col groups)
    const int lr   = lane >> 2;
    const int lc   = lane & 3;
    const int bm = blockIdx.y * 128;
    const int bn = blockIdx.x * 128;

    unsigned sbase = (unsigned)__cvta_generic_to_shared(smg);

    float acc[4][4][4];
    #pragma unroll
    for (int i = 0; i < 4; i++)
        #pragma unroll
        for (int j = 0; j < 4; j++)
            #pragma unroll
            for (int k = 0; k < 4; k++) acc[i][j][k] = 0.f;

    const int nK = DD / 32;
    gemm_stage(sbase, sbase + GA * 4, X, (const unsigned*)W, N, bm, bn, 0, tid);
    CPCOMMIT();
    gemm_stage(sbase + GSTG * 4, sbase + (GSTG + GA) * 4,
               X, (const unsigned*)W, N, bm, bn, 32, tid);
    CPCOMMIT();

    for (int i = 0; i < nK; i++) {
        if (i + 1 < nK) { CPWAIT(1); } else { CPWAIT(0); }
        __syncthreads();
        if (i + 2 < nK) {
            unsigned boff = ((i + 2) % 3) * GSTG * 4;
            gemm_stage(sbase + boff, sbase + boff + GA * 4,
                       X, (const unsigned*)W, N, bm, bn, (i + 2) * 32, tid);
            CPCOMMIT();
        }
        const unsigned* As = smg + (i % 3) * GSTG;
        const unsigned* Bs = As + GA;

        #pragma unroll
        for (int g = 0; g < 2; g++) {
            unsigned af[4][4], bf[4][2];
            #pragma unroll
            for (int mt = 0; mt < 4; mt++) {
                int r = wm * 64 + mt * 16 + lr;
                uint2 u1 = *(const uint2*)&As[r * 24 + 8 * g + 2 * lc];
                uint2 u2 = *(const uint2*)&As[(r + 8) * 24 + 8 * g + 2 * lc];
                af[mt][0] = u1.x; af[mt][1] = u2.x;
                af[mt][2] = u1.y; af[mt][3] = u2.y;
            }
            #pragma unroll
            for (int nt = 0; nt < 4; nt++) {
                int n = wn * 32 + nt * 8 + lr;
                bf[nt][0] = Bs[(8 * g + lc) * 136 + n];
                bf[nt][1] = Bs[(8 * g + lc + 4) * 136 + n];
            }
            #pragma unroll
            for (int mt = 0; mt < 4; mt++)
                #pragma unroll
                for (int nt = 0; nt < 4; nt++)
                    mma_f16(acc[mt][nt], af[mt], bf[nt]);
        }
    }

    #pragma unroll
    for (int mt = 0; mt < 4; mt++) {
        int r = bm + wm * 64 + mt * 16 + lr;
        #pragma unroll
        for (int nt = 0; nt < 4; nt++) {
            int base = bn + wn * 32 + nt * 8;
            int c0 = base + 2 * lc;
            float bv0 = bi[c0], bv1 = bi[c0 + 1];
            unsigned v0 = h2pack((acc[mt][nt][0] + bv0) * oscale,
                                 (acc[mt][nt][1] + bv1) * oscale);
            unsigned v1 = h2pack((acc[mt][nt][2] + bv0) * oscale,
                                 (acc[mt][nt][3] + bv1) * oscale);
            int idx;
            if (permv) {
                int L = (c0 & 15) >> 1;
                int phys = (L < 4) ? 2 * L : 2 * L - 7;
                idx = (c0 & ~15) + 2 * phys;
            } else {
                idx = c0;
            }
            *(unsigned*)(Y + (size_t)r * N + idx) = v0;
            *(unsigned*)(Y + (size_t)(r + 8) * N + idx) = v1;
        }
    }
}

// ---------------------------------------------------------------------------
// fp16 flash attention — byte-identical to round 14 (435us best config).
// ---------------------------------------------------------------------------
#define KSLOT 4608
#define VSLOT 5120
#define VBASE 18432
#define BARW  38912
#define ATTN_SMEM_BYTES (38944 * 4)

__global__ __launch_bounds__(256) void attn_f16(
    const __half* __restrict__ Q, const __half* __restrict__ K,
    const __half* __restrict__ Vt, float* __restrict__ O)
{
    extern __shared__ unsigned sm[];

    const int tid  = threadIdx.x;
    const int lane = tid & 31;
    const int wid  = tid >> 5;
    const int lr = lane >> 2;
    const int lc = lane & 3;
    const int r0 = 16 * wid + lr;
    const int q0 = blockIdx.x * 128;
    const int h  = blockIdx.y;
    const int b  = blockIdx.z;
    const int g  = h & (HKV - 1);

    const __half* Qb = Q + (size_t)b * SS * DD  + (size_t)h * HD;
    const __half* Kb = K + (size_t)b * SS * KVD + (size_t)g * HD;
    const unsigned* Vb2 = (const unsigned*)Vt + ((size_t)b * KVD + (size_t)g * HD) * (SS / 2);

    unsigned sbase = (unsigned)__cvta_generic_to_shared(sm);

    if (tid == 0) {
        #pragma unroll
        for (int s = 0; s < 4; s++) {
            MBAR_INIT(sbase + (BARW + 2 * s) * 4, 256);
            MBAR_INIT(sbase + (BARW + 8 + 2 * s) * 4, 256);
        }
    }

    #pragma unroll
    for (int it = 0; it < 8; it++) {
        int f = tid + it * 256;
        int q  = f >> 4;
        int ch = f & 15;
        CP16(sbase + (q * 72 + 4 * ch) * 4, Qb + (size_t)(q0 + q) * DD + ch * 8);
    }
    CPCOMMIT();
    CPWAIT(0);
    __syncthreads();

    unsigned qa[8][4];
    #pragma unroll
    for (int gch = 0; gch < 8; gch++) {
        uint2 u1 = *(const uint2*)&sm[r0 * 72 + 8 * gch + 2 * lc];
        uint2 u2 = *(const uint2*)&sm[(r0 + 8) * 72 + 8 * gch + 2 * lc];
        qa[gch][0] = u1.x; qa[gch][1] = u2.x;
        qa[gch][2] = u1.y; qa[gch][3] = u2.y;
    }
    __syncthreads();

    #pragma unroll
    for (int s = 0; s < 2; s++) {
        unsigned sKs = sbase + s * KSLOT * 4;
        unsigned sVs = sbase + (VBASE + s * VSLOT) * 4;
        #pragma unroll
        for (int it = 0; it < 4; it++) {
            int f = tid + it * 256;
            int key = f >> 4;
            int ch  = f & 15;
            CP16(sKs + (key * 72 + 4 * ch) * 4,
                 Kb + (size_t)(s * 64 + key) * KVD + ch * 8);
        }
        #pragma unroll
        for (int it = 0; it < 4; it++) {
            int f = tid + it * 256;
            int d  = f >> 3;
            int ch = f & 7;
            CP16(sVs + (d * 40 + 4 * ch) * 4,
                 Vb2 + (size_t)d * (SS / 2) + s * 32 + ch * 4);
        }
        CPASYNC_MBAR_ARRIVE(sbase + (BARW + 2 * s) * 4);
    }

    float o[16][4];
    #pragma unroll
    for (int dt = 0; dt < 16; dt++)
        #pragma unroll
        for (int k = 0; k < 4; k++) o[dt][k] = 0.f;
    float rm0 = -INFINITY, rm1 = -INFINITY, rl0 = 0.f, rl1 = 0.f;

    #pragma unroll 1
    for (int j = 0; j < NT / 2; j++) {
        #pragma unroll
        for (int pp = 0; pp < 2; pp++) {
            const int ft = 2 * j + 2 + pp;
            if (ft < NT) {
                const int slot = ft & 3;
                if (ft >= 4) MBAR_WAIT(sbase + (BARW + 8 + 2 * slot) * 4,
                                       (unsigned)(((ft >> 2) - 1) & 1));
                unsigned sKs = sbase + slot * KSLOT * 4;
                unsigned sVs = sbase + (VBASE + slot * VSLOT) * 4;
                #pragma unroll
                for (int it = 0; it < 4; it++) {
                    int f = tid + it * 256;
                    int key = f >> 4;
                    int ch  = f & 15;
                    CP16(sKs + (key * 72 + 4 * ch) * 4,
                         Kb + (size_t)(ft * 64 + key) * KVD + ch * 8);
                }
                #pragma unroll
                for (int it = 0; it < 4; it++) {
                    int f = tid + it * 256;
                    int d  = f >> 3;
                    int ch = f & 7;
                    CP16(sVs + (d * 40 + 4 * ch) * 4,
                         Vb2 + (size_t)d * (SS / 2) + ft * 32 + ch * 4);
                }
                CPASYNC_MBAR_ARRIVE(sbase + (BARW + 2 * slot) * 4);
            }
        }

        const int t0 = 2 * j;
        const int s0 = t0 & 3, s1 = (t0 + 1) & 3;
        const unsigned par = (unsigned)((t0 >> 2) & 1);

        MBAR_WAIT(sbase + (BARW + 2 * s0) * 4, par);
        const unsigned* KstA = sm + s0 * KSLOT;
        float saccA[8][4];
        #pragma unroll
        for (int nt = 0; nt < 8; nt++)
            #pragma unroll
            for (int k = 0; k < 4; k++) saccA[nt][k] = 0.f;
        #pragma unroll
        for (int gch = 0; gch < 8; gch++) {
            #pragma unroll
            for (int nt = 0; nt < 8; nt++) {
                uint2 bu = *(const uint2*)&KstA[(8 * nt + lr) * 72 + 8 * gch + 2 * lc];
                unsigned bf[2] = { bu.x, bu.y };
                mma_f16(saccA[nt], qa[gch], bf);
            }
        }

        MBAR_WAIT(sbase + (BARW + 2 * s1) * 4, par);
        const unsigned* KstB = sm + s1 * KSLOT;
        float saccB[8][4];
        #pragma unroll
        for (int nt = 0; nt < 8; nt++)
            #pragma unroll
            for (int k = 0; k < 4; k++) saccB[nt][k] = 0.f;
        #pragma unroll
        for (int gch = 0; gch < 8; gch++) {
            #pragma unroll
            for (int nt = 0; nt < 8; nt++) {
                uint2 bu = *(const uint2*)&KstB[(8 * nt + lr) * 72 + 8 * gch + 2 * lc];
                unsigned bf[2] = { bu.x, bu.y };
                mma_f16(saccB[nt], qa[gch], bf);
            }
        }

        float m0 = saccA[0][0], m1 = saccA[0][2];
        #pragma unroll
        for (int nt = 0; nt < 8; nt++) {
            m0 = fmaxf(m0, fmaxf(saccA[nt][0], saccA[nt][1]));
            m1 = fmaxf(m1, fmaxf(saccA[nt][2], saccA[nt][3]));
            m0 = fmaxf(m0, fmaxf(saccB[nt][0], saccB[nt][1]));
            m1 = fmaxf(m1, fmaxf(saccB[nt][2], saccB[nt][3]));
        }
        m0 = fmaxf(m0, __shfl_xor_sync(0xffffffffu, m0, 1));
        m0 = fmaxf(m0, __shfl_xor_sync(0xffffffffu, m0, 2));
        m1 = fmaxf(m1, __shfl_xor_sync(0xffffffffu, m1, 1));
        m1 = fmaxf(m1, __shfl_xor_sync(0xffffffffu, m1, 2));
        float mn0 = fmaxf(rm0, m0), mn1 = fmaxf(rm1, m1);
        float al0 = __expf(rm0 - mn0), al1 = __expf(rm1 - mn1);
        float sum0 = 0.f, sum1 = 0.f;
        unsigned paA[4][4], paB[4][4];
        #pragma unroll
        for (int jj = 0; jj < 4; jj++) {
            float e00 = __expf(saccA[2 * jj][0] - mn0);
            float e01 = __expf(saccA[2 * jj][1] - mn0);
            float e02 = __expf(saccA[2 * jj][2] - mn1);
            float e03 = __expf(saccA[2 * jj][3] - mn1);
            float e10 = __expf(saccA[2 * jj + 1][0] - mn0);
            float e11 = __expf(saccA[2 * jj + 1][1] - mn0);
            float e12 = __expf(saccA[2 * jj + 1][2] - mn1);
            float e13 = __expf(saccA[2 * jj + 1][3] - mn1);
            sum0 += e00 + e01 + e10 + e11;
            sum1 += e02 + e03 + e12 + e13;
            paA[jj][0] = h2pack(e00, e01);
            paA[jj][1] = h2pack(e02, e03);
            paA[jj][2] = h2pack(e10, e11);
            paA[jj][3] = h2pack(e12, e13);
        }
        #pragma unroll
        for (int jj = 0; jj < 4; jj++) {
            float e00 = __expf(saccB[2 * jj][0] - mn0);
            float e01 = __expf(saccB[2 * jj][1] - mn0);
            float e02 = __expf(saccB[2 * jj][2] - mn1);
            float e03 = __expf(saccB[2 * jj][3] - mn1);
            float e10 = __expf(saccB[2 * jj + 1][0] - mn0);
            float e11 = __expf(saccB[2 * jj + 1][1] - mn0);
            float e12 = __expf(saccB[2 * jj + 1][2] - mn1);
            float e13 = __expf(saccB[2 * jj + 1][3] - mn1);
            sum0 += e00 + e01 + e10 + e11;
            sum1 += e02 + e03 + e12 + e13;
            paB[jj][0] = h2pack(e00, e01);
            paB[jj][1] = h2pack(e02, e03);
            paB[jj][2] = h2pack(e10, e11);
            paB[jj][3] = h2pack(e12, e13);
        }
        sum0 += __shfl_xor_sync(0xffffffffu, sum0, 1);
        sum0 += __shfl_xor_sync(0xffffffffu, sum0, 2);
        sum1 += __shfl_xor_sync(0xffffffffu, sum1, 1);
        sum1 += __shfl_xor_sync(0xffffffffu, sum1, 2);
        rl0 = rl0 * al0 + sum0;  rm0 = mn0;
        rl1 = rl1 * al1 + sum1;  rm1 = mn1;
        #pragma unroll
        for (int dt = 0; dt < 16; dt++) {
            o[dt][0] *= al0;  o[dt][1] *= al0;
            o[dt][2] *= al1;  o[dt][3] *= al1;
        }

        const unsigned* VtsA = sm + VBASE + s0 * VSLOT;
        #pragma unroll
        for (int jj = 0; jj < 4; jj++) {
            #pragma unroll
            for (int dt = 0; dt < 16; dt++) {
                uint2 vu = *(const uint2*)&VtsA[(8 * dt + lr) * 40 + 8 * jj + 2 * lc];
                unsigned bf[2] = { vu.x, vu.y };
                mma_f16(o[dt], paA[jj], bf);
            }
        }
        MBAR_ARRIVE(sbase + (BARW + 8 + 2 * s0) * 4);

        const unsigned* VtsB = sm + VBASE + s1 * VSLOT;
        #pragma unroll
        for (int jj = 0; jj < 4; jj++) {
            #pragma unroll
            for (int dt = 0; dt < 16; dt++) {
                uint2 vu = *(const uint2*)&VtsB[(8 * dt + lr) * 40 + 8 * jj + 2 * lc];
                unsigned bf[2] = { vu.x, vu.y };
                mma_f16(o[dt], paB[jj], bf);
            }
        }
        MBAR_ARRIVE(sbase + (BARW + 8 + 2 * s1) * 4);
    }

    float* Ob = O + (size_t)b * SS * DD + (size_t)h * HD;
    float inv0 = 1.f / rl0, inv1 = 1.f / rl1;
    #pragma unroll
    for (int dt = 0; dt < 16; dt++) {
        int cc = 8 * dt + 2 * lc;
        *(float2*)(Ob + (size_t)(q0 + r0) * DD + cc) =
            make_float2(o[dt][0] * inv0, o[dt][1] * inv0);
        *(float2*)(Ob + (size_t)(q0 + r0 + 8) * DD + cc) =
            make_float2(o[dt][2] * inv1, o[dt][3] * inv1);
    }
}

// ---------------------------------------------------------------------------
extern "C" void kernel_launch(void* const* d_in, const int* in_sizes, int n_in,
                              void* d_out, int out_size)
{
    (void)in_sizes; (void)n_in; (void)out_size;
    const float* H  = (const float*)d_in[0];
    const float* Wq = (const float*)d_in[1];
    const float* bq = (const float*)d_in[2];
    const float* Wk = (const float*)d_in[3];
    const float* bk = (const float*)d_in[4];
    const float* Wv = (const float*)d_in[5];
    const float* bv = (const float*)d_in[6];
    float* out = (float*)d_out;

    static cudaStream_t s2 = 0;
    static cudaEvent_t eFork = 0, eH = 0, eKV = 0;
    if (s2 == 0) {
        cudaStreamCreateWithFlags(&s2, cudaStreamNonBlocking);
        cudaEventCreateWithFlags(&eFork, cudaEventDisableTiming);
        cudaEventCreateWithFlags(&eH,    cudaEventDisableTiming);
        cudaEventCreateWithFlags(&eKV,   cudaEventDisableTiming);
    }

    __half *Qp, *Kp, *Vp, *Vtp, *Hp, *Wqp, *Wkp, *Wvp;
    cudaGetSymbolAddress((void**)&Qp,  g_Q);
    cudaGetSymbolAddress((void**)&Kp,  g_K);
    cudaGetSymbolAddress((void**)&Vp,  g_V);
    cudaGetSymbolAddress((void**)&Vtp, g_Vt);
    cudaGetSymbolAddress((void**)&Hp,  g_H);
    cudaGetSymbolAddress((void**)&Wqp, g_Wq);
    cudaGetSymbolAddress((void**)&Wkp, g_Wk);
    cudaGetSymbolAddress((void**)&Wvp, g_Wv);

    cudaFuncSetAttribute(gemm_f16,
                         cudaFuncAttributeMaxDynamicSharedMemorySize, GEMM_SMEM_BYTES);
    cudaFuncSetAttribute(attn_f16,
                         cudaFuncAttributeMaxDynamicSharedMemorySize, ATTN_SMEM_BYTES);

    const float scale = 0.08838834764831845f;  // 1/sqrt(128)
    const int nb = 148 * 8;

    cudaEventRecord(eFork, 0);
    cudaStreamWaitEvent(s2, eFork, 0);

    // Stream 0: H cvt (#1), Wq cvt (#2)
    cvt_h<<<nb, 256>>>(Hp, H, (int)((size_t)MM * DD / 16));
    cvt_w<<<nb, 256>>>(Wqp, Wq, DD / 2, DD);
    cudaEventRecord(eH, 0);

    // Stream s2: fused Wk/Wv cvt (#3), then wait for H.
    cvt_w_kv<<<dim3(nb, 1, 2), 256, 0, s2>>>(Wkp, Wk, Wvp, Wv);
    cudaStreamWaitEvent(s2, eH, 0);

    // Stream 0: Q projection (#4 — profiled).
    gemm_f16<<<dim3(DD / 128, MM / 128, 1), 256, GEMM_SMEM_BYTES>>>(
        Hp, Wqp, bq, Qp, Wkp, bk, Kp, Wvp, bv, Vp, scale, 0);

    // Stream s2: K + V projections, then V transpose.
    gemm_f16<<<dim3(KVD / 128, MM / 128, 2), 256, GEMM_SMEM_BYTES, s2>>>(
        Hp, Wqp, bq, Qp, Wkp, bk, Kp, Wvp, bv, Vp, scale, 1);
    transpose_v<<<dim3(SS / 64, KVD / 32, BB), dim3(32, 8), 0, s2>>>(Vtp, Vp);
    cudaEventRecord(eKV, s2);

    cudaStreamWaitEvent(0, eKV, 0);
    attn_f16<<<dim3(SS / 128, HQ, BB), 256, ATTN_SMEM_BYTES>>>(Qp, Kp, Vtp, out);
}

// round 17
// speedup vs baseline: 1.0897x; 1.0519x over previous
#include <cuda_runtime.h>
#include <cuda_fp16.h>
#include <math.h>

#define BB   2
#define SS   2048
#define DD   2048
#define HQ   16
#define HKV  4
#define HD   128
#define KVD  512
#define MM   (BB*SS)
#define NT   (SS/64)

// Scratch (device globals) — fp16 operands, fp32 I/O
__device__ __half g_Q[(size_t)MM * DD];
__device__ __half g_K[(size_t)MM * KVD];
__device__ __half g_V[(size_t)MM * KVD];
__device__ __half g_Vt[(size_t)BB * KVD * SS];
__device__ __half g_H[(size_t)MM * DD];
__device__ __half g_Wq[(size_t)DD * DD];    // h2 [k/2][n]
__device__ __half g_Wk[(size_t)DD * KVD];
__device__ __half g_Wv[(size_t)DD * KVD];

__device__ __forceinline__ unsigned h2pack(float lo, float hi) {
    __half2 h = __floats2half2_rn(lo, hi);
    return *reinterpret_cast<unsigned*>(&h);
}
__device__ __forceinline__ unsigned ex2h2(unsigned x) {
    unsigned r;
    asm("ex2.approx.f16x2 %0, %1;" : "=r"(r) : "r"(x));
    return r;
}
__device__ __forceinline__ float ex2f(float x) {
    float r;
    asm("ex2.approx.ftz.f32 %0, %1;" : "=f"(r) : "f"(x));
    return r;
}

__device__ __forceinline__ void mma_f16(float c[4], const unsigned a[4], const unsigned b[2]) {
    asm volatile(
        "mma.sync.aligned.m16n8k16.row.col.f32.f16.f16.f32 "
        "{%0,%1,%2,%3},{%4,%5,%6,%7},{%8,%9},{%0,%1,%2,%3};"
        : "+f"(c[0]), "+f"(c[1]), "+f"(c[2]), "+f"(c[3])
        : "r"(a[0]), "r"(a[1]), "r"(a[2]), "r"(a[3]), "r"(b[0]), "r"(b[1]));
}

#define CP16(dst, src) \
    asm volatile("cp.async.cg.shared.global [%0], [%1], 16;" :: "r"(dst), "l"(src))
#define CPCOMMIT() asm volatile("cp.async.commit_group;")
#define CPWAIT(N)  asm volatile("cp.async.wait_group %0;" :: "n"(N))

#define MBAR_INIT(addr, cnt) \
    asm volatile("mbarrier.init.shared.b64 [%0], %1;" :: "r"(addr), "r"(cnt) : "memory")
#define MBAR_ARRIVE(addr) \
    asm volatile("mbarrier.arrive.shared.b64 _, [%0];" :: "r"(addr) : "memory")
#define CPASYNC_MBAR_ARRIVE(addr) \
    asm volatile("cp.async.mbarrier.arrive.noinc.shared.b64 [%0];" :: "r"(addr) : "memory")

#define MBAR_WAIT(addr, par) do { \
    unsigned _m = (addr), _p = (par), _d; \
    asm volatile("{\n\t.reg .pred p;\n\t" \
        "mbarrier.try_wait.parity.acquire.cta.shared::cta.b64 p, [%1], %2;\n\t" \
        "selp.b32 %0, 1, 0, p;\n\t}" : "=r"(_d) : "r"(_m), "r"(_p) : "memory"); \
    if (!_d) { \
        asm volatile("{\n\t.reg .pred P1;\n\t" \
            "WL%=:\n\t" \
            "mbarrier.try_wait.parity.acquire.cta.shared::cta.b64 P1, [%0], %1, 0x989680;\n\t" \
            "@P1 bra.uni WD%=;\n\t" \
            "bra.uni WL%=;\n\t" \
            "WD%=:\n\t}" :: "r"(_m), "r"(_p) : "memory"); \
    } \
} while (0)

// ---------------------------------------------------------------------------
// H: fp32 -> fp16, pairs permuted [P0,P4,P1,P5,P2,P6,P3,P7] per 16-value group.
// ---------------------------------------------------------------------------
__global__ void cvt_h(__half* __restrict__ dst, const float* __restrict__ src, int n16)
{
    int i = blockIdx.x * blockDim.x + threadIdx.x;
    const int stride = gridDim.x * blockDim.x;
    for (; i < n16; i += stride) {
        const float4* s = (const float4*)src + 4 * (size_t)i;
        float4 s0 = s[0], s1 = s[1], s2 = s[2], s3 = s[3];
        uint4 o0, o1;
        o0.x = h2pack(s0.x, s0.y);
        o0.y = h2pack(s2.x, s2.y);
        o0.z = h2pack(s0.z, s0.w);
        o0.w = h2pack(s2.z, s2.w);
        o1.x = h2pack(s1.x, s1.y);
        o1.y = h2pack(s3.x, s3.y);
        o1.z = h2pack(s1.z, s1.w);
        o1.w = h2pack(s3.z, s3.w);
        uint4* o = (uint4*)dst + 2 * (size_t)i;
        o[0] = o0;
        o[1] = o1;
    }
}

// ---------------------------------------------------------------------------
// W: fp32 [k][n] -> h2 [k/2][n]
// ---------------------------------------------------------------------------
__device__ __forceinline__ void cvt_w_body(
    __half* __restrict__ dst, const float* __restrict__ src, int K2, int N)
{
    int j = blockIdx.x * blockDim.x + threadIdx.x;
    const int stride = gridDim.x * blockDim.x;
    const int nq = N / 4;
    const int total = K2 * nq;
    for (; j < total; j += stride) {
        int i  = j / nq;
        int n4 = (j % nq) * 4;
        float4 a = *(const float4*)(src + (size_t)(2 * i) * N + n4);
        float4 b = *(const float4*)(src + (size_t)(2 * i + 1) * N + n4);
        uint4 o;
        o.x = h2pack(a.x, b.x);
        o.y = h2pack(a.y, b.y);
        o.z = h2pack(a.z, b.z);
        o.w = h2pack(a.w, b.w);
        *((uint4*)dst + (size_t)i * nq + (n4 >> 2)) = o;
    }
}

__global__ void cvt_w(__half* __restrict__ dst, const float* __restrict__ src,
                      int K2, int N)
{
    cvt_w_body(dst, src, K2, N);
}

__global__ void cvt_w_kv(
    __half* __restrict__ dk, const float* __restrict__ sk,
    __half* __restrict__ dv, const float* __restrict__ sv)
{
    if (blockIdx.z == 0) cvt_w_body(dk, sk, DD / 2, KVD);
    else                 cvt_w_body(dv, sv, DD / 2, KVD);
}

// ---------------------------------------------------------------------------
// V half [b][s][gd] -> Vt h2 [b*512+gd][s/2], s pairs permuted per 16-s group.
// ---------------------------------------------------------------------------
__global__ void transpose_v(__half* __restrict__ Vt, const __half* __restrict__ V)
{
    __shared__ __half t[64][36];
    const int s0 = blockIdx.x * 64, gd0 = blockIdx.y * 32, b = blockIdx.z;
    #pragma unroll
    for (int i = 0; i < 8; i++) {
        int e = (threadIdx.y + i * 8) * 32 + threadIdx.x;
        int srow = e >> 5, gcol = e & 31;
        t[srow][gcol] = V[((size_t)b * SS + s0 + srow) * KVD + gd0 + gcol];
    }
    __syncthreads();
    const int x = threadIdx.x;
    const int grp = x >> 3, qq = x & 7;
    const int lp = (qq & 1) ? (qq >> 1) + 4 : (qq >> 1);
    const int sl = grp * 16 + 2 * lp;
    unsigned* Vt2 = (unsigned*)Vt;
    #pragma unroll
    for (int i = 0; i < 4; i++) {
        int gd = threadIdx.y + i * 8;
        float lo = __half2float(t[sl][gd]);
        float hi = __half2float(t[sl + 1][gd]);
        Vt2[((size_t)b * KVD + gd0 + gd) * (SS / 2) + (s0 >> 1) + x] = h2pack(lo, hi);
    }
}

// ---------------------------------------------------------------------------
// fp16 GEMM + bias — byte-identical to round 16 (2 CTAs/SM).
// ---------------------------------------------------------------------------
#define GA 3072
#define GB 2176
#define GSTG (GA + GB)
#define GEMM_SMEM_BYTES (GSTG * 3 * 4)

__device__ __forceinline__ void gemm_stage(
    unsigned sA, unsigned sB, const __half* __restrict__ X, const unsigned* __restrict__ W2,
    int N, int bm, int bn, int k0, int tid)
{
    #pragma unroll
    for (int it = 0; it < 2; it++) {
        int f = tid + it * 256;
        int m  = f >> 2;
        int ch = f & 3;
        CP16(sA + (m * 24 + 4 * ch) * 4, X + (size_t)(bm + m) * DD + k0 + ch * 8);
    }
    const int k02 = k0 >> 1;
    #pragma unroll
    for (int it = 0; it < 2; it++) {
        int f = tid + it * 256;
        int kk2 = f >> 5;
        int nq  = (f & 31) * 4;
        CP16(sB + (kk2 * 136 + nq) * 4, W2 + (size_t)(k02 + kk2) * N + bn + nq);
    }
}

__global__ __launch_bounds__(256, 2) void gemm_f16(
    const __half* __restrict__ X,
    const __half* __restrict__ Wq, const float* __restrict__ bq, __half* __restrict__ Yq,
    const __half* __restrict__ Wk, const float* __restrict__ bk, __half* __restrict__ Yk,
    const __half* __restrict__ Wv, const float* __restrict__ bv, __half* __restrict__ Yv,
    float qscale, int zoff)
{
    const int z = blockIdx.z + zoff;
    const __half* __restrict__ W  = (z == 0) ? Wq : (z == 1) ? Wk : Wv;
    const float*  __restrict__ bi = (z == 0) ? bq : (z == 1) ? bk : bv;
    __half*       __restrict__ Y  = (z == 0) ? Yq : (z == 1) ? Yk : Yv;
    const int   N      = (z == 0) ? DD : KVD;
    const float oscale = (z == 0) ? qscale : 1.0f;
    const int   permv  = (z == 2) ? 0 : 1;

    extern __shared__ unsigned smg[];
    const int tid  = threadIdx.x;
    const int lane = tid & 31;
    const int wid  = tid >> 5;
    const int wm   = wid & 1;
    const int wn   = wid >> 1;
    const int lr   = lane >> 2;
    const int lc   = lane & 3;
    const int bm = blockIdx.y * 128;
    const int bn = blockIdx.x * 128;

    unsigned sbase = (unsigned)__cvta_generic_to_shared(smg);

    float acc[4][4][4];
    #pragma unroll
    for (int i = 0; i < 4; i++)
        #pragma unroll
        for (int j = 0; j < 4; j++)
            #pragma unroll
            for (int k = 0; k < 4; k++) acc[i][j][k] = 0.f;

    const int nK = DD / 32;
    gemm_stage(sbase, sbase + GA * 4, X, (const unsigned*)W, N, bm, bn, 0, tid);
    CPCOMMIT();
    gemm_stage(sbase + GSTG * 4, sbase + (GSTG + GA) * 4,
               X, (const unsigned*)W, N, bm, bn, 32, tid);
    CPCOMMIT();

    for (int i = 0; i < nK; i++) {
        if (i + 1 < nK) { CPWAIT(1); } else { CPWAIT(0); }
        __syncthreads();
        if (i + 2 < nK) {
            unsigned boff = ((i + 2) % 3) * GSTG * 4;
            gemm_stage(sbase + boff, sbase + boff + GA * 4,
                       X, (const unsigned*)W, N, bm, bn, (i + 2) * 32, tid);
            CPCOMMIT();
        }
        const unsigned* As = smg + (i % 3) * GSTG;
        const unsigned* Bs = As + GA;

        #pragma unroll
        for (int g = 0; g < 2; g++) {
            unsigned af[4][4], bf[4][2];
            #pragma unroll
            for (int mt = 0; mt < 4; mt++) {
                int r = wm * 64 + mt * 16 + lr;
                uint2 u1 = *(const uint2*)&As[r * 24 + 8 * g + 2 * lc];
                uint2 u2 = *(const uint2*)&As[(r + 8) * 24 + 8 * g + 2 * lc];
                af[mt][0] = u1.x; af[mt][1] = u2.x;
                af[mt][2] = u1.y; af[mt][3] = u2.y;
            }
            #pragma unroll
            for (int nt = 0; nt < 4; nt++) {
                int n = wn * 32 + nt * 8 + lr;
                bf[nt][0] = Bs[(8 * g + lc) * 136 + n];
                bf[nt][1] = Bs[(8 * g + lc + 4) * 136 + n];
            }
            #pragma unroll
            for (int mt = 0; mt < 4; mt++)
                #pragma unroll
                for (int nt = 0; nt < 4; nt++)
                    mma_f16(acc[mt][nt], af[mt], bf[nt]);
        }
    }

    #pragma unroll
    for (int mt = 0; mt < 4; mt++) {
        int r = bm + wm * 64 + mt * 16 + lr;
        #pragma unroll
        for (int nt = 0; nt < 4; nt++) {
            int base = bn + wn * 32 + nt * 8;
            int c0 = base + 2 * lc;
            float bv0 = bi[c0], bv1 = bi[c0 + 1];
            unsigned v0 = h2pack((acc[mt][nt][0] + bv0) * oscale,
                                 (acc[mt][nt][1] + bv1) * oscale);
            unsigned v1 = h2pack((acc[mt][nt][2] + bv0) * oscale,
                                 (acc[mt][nt][3] + bv1) * oscale);
            int idx;
            if (permv) {
                int L = (c0 & 15) >> 1;
                int phys = (L < 4) ? 2 * L : 2 * L - 7;
                idx = (c0 & ~15) + 2 * phys;
            } else {
                idx = c0;
            }
            *(unsigned*)(Y + (size_t)r * N + idx) = v0;
            *(unsigned*)(Y + (size_t)(r + 8) * N + idx) = v1;
        }
    }
}

// ---------------------------------------------------------------------------
// fp16 flash attention, log2-domain softmax with ex2.f16x2 and l-via-MMA
// (ones column appended to V). Scores arrive pre-scaled by scale*log2(e).
// SMEM: K 4x4608 | Vt 4x(136 rows x 40) = 5440 | bars.
// Vt rows 128..135 of every slot are static: row128=ones, rest zero.
// ---------------------------------------------------------------------------
#define KSLOT 4608
#define VSLOT 5440
#define VBASE 18432
#define BARW  40192
#define ATTN_SMEM_BYTES (40224 * 4)

__global__ __launch_bounds__(256) void attn_f16(
    const __half* __restrict__ Q, const __half* __restrict__ K,
    const __half* __restrict__ Vt, float* __restrict__ O)
{
    extern __shared__ unsigned sm[];

    const int tid  = threadIdx.x;
    const int lane = tid & 31;
    const int wid  = tid >> 5;
    const int lr = lane >> 2;
    const int lc = lane & 3;
    const int r0 = 16 * wid + lr;
    const int q0 = blockIdx.x * 128;
    const int h  = blockIdx.y;
    const int b  = blockIdx.z;
    const int g  = h & (HKV - 1);

    const __half* Qb = Q + (size_t)b * SS * DD  + (size_t)h * HD;
    const __half* Kb = K + (size_t)b * SS * KVD + (size_t)g * HD;
    const unsigned* Vb2 = (const unsigned*)Vt + ((size_t)b * KVD + (size_t)g * HD) * (SS / 2);

    unsigned sbase = (unsigned)__cvta_generic_to_shared(sm);

    if (tid == 0) {
        #pragma unroll
        for (int s = 0; s < 4; s++) {
            MBAR_INIT(sbase + (BARW + 2 * s) * 4, 256);
            MBAR_INIT(sbase + (BARW + 8 + 2 * s) * 4, 256);
        }
    }
    // Static ones/zero rows (128..135) of each V slot.
    for (int idx = tid; idx < 4 * 8 * 40; idx += 256) {
        int slot = idx / 320;
        int rem  = idx % 320;
        int row  = 128 + rem / 40;
        int col  = rem % 40;
        sm[VBASE + slot * VSLOT + row * 40 + col] = (row == 128) ? 0x3C003C00u : 0u;
    }

    #pragma unroll
    for (int it = 0; it < 8; it++) {
        int f = tid + it * 256;
        int q  = f >> 4;
        int ch = f & 15;
        CP16(sbase + (q * 72 + 4 * ch) * 4, Qb + (size_t)(q0 + q) * DD + ch * 8);
    }
    CPCOMMIT();
    CPWAIT(0);
    __syncthreads();

    unsigned qa[8][4];
    #pragma unroll
    for (int gch = 0; gch < 8; gch++) {
        uint2 u1 = *(const uint2*)&sm[r0 * 72 + 8 * gch + 2 * lc];
        uint2 u2 = *(const uint2*)&sm[(r0 + 8) * 72 + 8 * gch + 2 * lc];
        qa[gch][0] = u1.x; qa[gch][1] = u2.x;
        qa[gch][2] = u1.y; qa[gch][3] = u2.y;
    }
    __syncthreads();

    #pragma unroll
    for (int s = 0; s < 2; s++) {
        unsigned sKs = sbase + s * KSLOT * 4;
        unsigned sVs = sbase + (VBASE + s * VSLOT) * 4;
        #pragma unroll
        for (int it = 0; it < 4; it++) {
            int f = tid + it * 256;
            int key = f >> 4;
            int ch  = f & 15;
            CP16(sKs + (key * 72 + 4 * ch) * 4,
                 Kb + (size_t)(s * 64 + key) * KVD + ch * 8);
        }
        #pragma unroll
        for (int it = 0; it < 4; it++) {
            int f = tid + it * 256;
            int d  = f >> 3;
            int ch = f & 7;
            CP16(sVs + (d * 40 + 4 * ch) * 4,
                 Vb2 + (size_t)d * (SS / 2) + s * 32 + ch * 4);
        }
        CPASYNC_MBAR_ARRIVE(sbase + (BARW + 2 * s) * 4);
    }

    float o[17][4];   // o[16] = l column (V ones-column)
    #pragma unroll
    for (int dt = 0; dt < 17; dt++)
        #pragma unroll
        for (int k = 0; k < 4; k++) o[dt][k] = 0.f;
    float rm0 = -INFINITY, rm1 = -INFINITY;   // log2-domain running max

    #pragma unroll 1
    for (int j = 0; j < NT / 2; j++) {
        #pragma unroll
        for (int pp = 0; pp < 2; pp++) {
            const int ft = 2 * j + 2 + pp;
            if (ft < NT) {
                const int slot = ft & 3;
                if (ft >= 4) MBAR_WAIT(sbase + (BARW + 8 + 2 * slot) * 4,
                                       (unsigned)(((ft >> 2) - 1) & 1));
                unsigned sKs = sbase + slot * KSLOT * 4;
                unsigned sVs = sbase + (VBASE + slot * VSLOT) * 4;
                #pragma unroll
                for (int it = 0; it < 4; it++) {
                    int f = tid + it * 256;
                    int key = f >> 4;
                    int ch  = f & 15;
                    CP16(sKs + (key * 72 + 4 * ch) * 4,
                         Kb + (size_t)(ft * 64 + key) * KVD + ch * 8);
                }
                #pragma unroll
                for (int it = 0; it < 4; it++) {
                    int f = tid + it * 256;
                    int d  = f >> 3;
                    int ch = f & 7;
                    CP16(sVs + (d * 40 + 4 * ch) * 4,
                         Vb2 + (size_t)d * (SS / 2) + ft * 32 + ch * 4);
                }
                CPASYNC_MBAR_ARRIVE(sbase + (BARW + 2 * slot) * 4);
            }
        }

        const int t0 = 2 * j;
        const int s0 = t0 & 3, s1 = (t0 + 1) & 3;
        const unsigned par = (unsigned)((t0 >> 2) & 1);

        MBAR_WAIT(sbase + (BARW + 2 * s0) * 4, par);
        const unsigned* KstA = sm + s0 * KSLOT;
        float saccA[8][4];
        #pragma unroll
        for (int nt = 0; nt < 8; nt++)
            #pragma unroll
            for (int k = 0; k < 4; k++) saccA[nt][k] = 0.f;
        #pragma unroll
        for (int gch = 0; gch < 8; gch++) {
            #pragma unroll
            for (int nt = 0; nt < 8; nt++) {
                uint2 bu = *(const uint2*)&KstA[(8 * nt + lr) * 72 + 8 * gch + 2 * lc];
                unsigned bf[2] = { bu.x, bu.y };
                mma_f16(saccA[nt], qa[gch], bf);
            }
        }

        MBAR_WAIT(sbase + (BARW + 2 * s1) * 4, par);
        const unsigned* KstB = sm + s1 * KSLOT;
        float saccB[8][4];
        #pragma unroll
        for (int nt = 0; nt < 8; nt++)
            #pragma unroll
            for (int k = 0; k < 4; k++) saccB[nt][k] = 0.f;
        #pragma unroll
        for (int gch = 0; gch < 8; gch++) {
            #pragma unroll
            for (int nt = 0; nt < 8; nt++) {
                uint2 bu = *(const uint2*)&KstB[(8 * nt + lr) * 72 + 8 * gch + 2 * lc];
                unsigned bf[2] = { bu.x, bu.y };
                mma_f16(saccB[nt], qa[gch], bf);
            }
        }

        // ---- joint 128-key softmax in log2 domain ----
        float m0 = saccA[0][0], m1 = saccA[0][2];
        #pragma unroll
        for (int nt = 0; nt < 8; nt++) {
            m0 = fmaxf(m0, fmaxf(saccA[nt][0], saccA[nt][1]));
            m1 = fmaxf(m1, fmaxf(saccA[nt][2], saccA[nt][3]));
            m0 = fmaxf(m0, fmaxf(saccB[nt][0], saccB[nt][1]));
            m1 = fmaxf(m1, fmaxf(saccB[nt][2], saccB[nt][3]));
        }
        m0 = fmaxf(m0, __shfl_xor_sync(0xffffffffu, m0, 1));
        m0 = fmaxf(m0, __shfl_xor_sync(0xffffffffu, m0, 2));
        m1 = fmaxf(m1, __shfl_xor_sync(0xffffffffu, m1, 1));
        m1 = fmaxf(m1, __shfl_xor_sync(0xffffffffu, m1, 2));
        float mn0 = fmaxf(rm0, m0), mn1 = fmaxf(rm1, m1);
        float al0 = ex2f(rm0 - mn0), al1 = ex2f(rm1 - mn1);
        rm0 = mn0;  rm1 = mn1;

        unsigned paA[4][4], paB[4][4];
        #pragma unroll
        for (int jj = 0; jj < 4; jj++) {
            paA[jj][0] = ex2h2(h2pack(saccA[2*jj][0] - mn0, saccA[2*jj][1] - mn0));
            paA[jj][1] = ex2h2(h2pack(saccA[2*jj][2] - mn1, saccA[2*jj][3] - mn1));
            paA[jj][2] = ex2h2(h2pack(saccA[2*jj+1][0] - mn0, saccA[2*jj+1][1] - mn0));
            paA[jj][3] = ex2h2(h2pack(saccA[2*jj+1][2] - mn1, saccA[2*jj+1][3] - mn1));
            paB[jj][0] = ex2h2(h2pack(saccB[2*jj][0] - mn0, saccB[2*jj][1] - mn0));
            paB[jj][1] = ex2h2(h2pack(saccB[2*jj][2] - mn1, saccB[2*jj][3] - mn1));
            paB[jj][2] = ex2h2(h2pack(saccB[2*jj+1][0] - mn0, saccB[2*jj+1][1] - mn0));
            paB[jj][3] = ex2h2(h2pack(saccB[2*jj+1][2] - mn1, saccB[2*jj+1][3] - mn1));
        }

        #pragma unroll
        for (int dt = 0; dt < 17; dt++) {
            o[dt][0] *= al0;  o[dt][1] *= al0;
            o[dt][2] *= al1;  o[dt][3] *= al1;
        }

        // ---- O (incl. l column dt=16) += P V ----
        const unsigned* VtsA = sm + VBASE + s0 * VSLOT;
        #pragma unroll
        for (int jj = 0; jj < 4; jj++) {
            #pragma unroll
            for (int dt = 0; dt < 17; dt++) {
                uint2 vu = *(const uint2*)&VtsA[(8 * dt + lr) * 40 + 8 * jj + 2 * lc];
                unsigned bf[2] = { vu.x, vu.y };
                mma_f16(o[dt], paA[jj], bf);
            }
        }
        MBAR_ARRIVE(sbase + (BARW + 8 + 2 * s0) * 4);

        const unsigned* VtsB = sm + VBASE + s1 * VSLOT;
        #pragma unroll
        for (int jj = 0; jj < 4; jj++) {
            #pragma unroll
            for (int dt = 0; dt < 17; dt++) {
                uint2 vu = *(const uint2*)&VtsB[(8 * dt + lr) * 40 + 8 * jj + 2 * lc];
                unsigned bf[2] = { vu.x, vu.y };
                mma_f16(o[dt], paB[jj], bf);
            }
        }
        MBAR_ARRIVE(sbase + (BARW + 8 + 2 * s1) * 4);
    }

    // Epilogue: l lives in o[16][0]/o[16][2] of lanes with lc==0.
    float l0 = __shfl_sync(0xffffffffu, o[16][0], lane & ~3);
    float l1 = __shfl_sync(0xffffffffu, o[16][2], lane & ~3);
    float inv0 = 1.f / l0, inv1 = 1.f / l1;
    float* Ob = O + (size_t)b * SS * DD + (size_t)h * HD;
    #pragma unroll
    for (int dt = 0; dt < 16; dt++) {
        int cc = 8 * dt + 2 * lc;
        *(float2*)(Ob + (size_t)(q0 + r0) * DD + cc) =
            make_float2(o[dt][0] * inv0, o[dt][1] * inv0);
        *(float2*)(Ob + (size_t)(q0 + r0 + 8) * DD + cc) =
            make_float2(o[dt][2] * inv1, o[dt][3] * inv1);
    }
}

// ---------------------------------------------------------------------------
extern "C" void kernel_launch(void* const* d_in, const int* in_sizes, int n_in,
                              void* d_out, int out_size)
{
    (void)in_sizes; (void)n_in; (void)out_size;
    const float* H  = (const float*)d_in[0];
    const float* Wq = (const float*)d_in[1];
    const float* bq = (const float*)d_in[2];
    const float* Wk = (const float*)d_in[3];
    const float* bk = (const float*)d_in[4];
    const float* Wv = (const float*)d_in[5];
    const float* bv = (const float*)d_in[6];
    float* out = (float*)d_out;

    static cudaStream_t s2 = 0;
    static cudaEvent_t eFork = 0, eH = 0, eKV = 0;
    if (s2 == 0) {
        cudaStreamCreateWithFlags(&s2, cudaStreamNonBlocking);
        cudaEventCreateWithFlags(&eFork, cudaEventDisableTiming);
        cudaEventCreateWithFlags(&eH,    cudaEventDisableTiming);
        cudaEventCreateWithFlags(&eKV,   cudaEventDisableTiming);
    }

    __half *Qp, *Kp, *Vp, *Vtp, *Hp, *Wqp, *Wkp, *Wvp;
    cudaGetSymbolAddress((void**)&Qp,  g_Q);
    cudaGetSymbolAddress((void**)&Kp,  g_K);
    cudaGetSymbolAddress((void**)&Vp,  g_V);
    cudaGetSymbolAddress((void**)&Vtp, g_Vt);
    cudaGetSymbolAddress((void**)&Hp,  g_H);
    cudaGetSymbolAddress((void**)&Wqp, g_Wq);
    cudaGetSymbolAddress((void**)&Wkp, g_Wk);
    cudaGetSymbolAddress((void**)&Wvp, g_Wv);

    cudaFuncSetAttribute(gemm_f16,
                         cudaFuncAttributeMaxDynamicSharedMemorySize, GEMM_SMEM_BYTES);
    cudaFuncSetAttribute(attn_f16,
                         cudaFuncAttributeMaxDynamicSharedMemorySize, ATTN_SMEM_BYTES);

    // Q pre-scale includes log2(e) so attention scores are in log2 domain.
    const float qscale = 0.08838834764831845f * 1.4426950408889634f;
    const int nb = 148 * 8;

    cudaEventRecord(eFork, 0);
    cudaStreamWaitEvent(s2, eFork, 0);

    cvt_h<<<nb, 256>>>(Hp, H, (int)((size_t)MM * DD / 16));
    cvt_w<<<nb, 256>>>(Wqp, Wq, DD / 2, DD);
    cudaEventRecord(eH, 0);

    cvt_w_kv<<<dim3(nb, 1, 2), 256, 0, s2>>>(Wkp, Wk, Wvp, Wv);
    cudaStreamWaitEvent(s2, eH, 0);

    gemm_f16<<<dim3(DD / 128, MM / 128, 1), 256, GEMM_SMEM_BYTES>>>(
        Hp, Wqp, bq, Qp, Wkp, bk, Kp, Wvp, bv, Vp, qscale, 0);

    gemm_f16<<<dim3(KVD / 128, MM / 128, 2), 256, GEMM_SMEM_BYTES, s2>>>(
        Hp, Wqp, bq, Qp, Wkp, bk, Kp, Wvp, bv, Vp, qscale, 1);
    transpose_v<<<dim3(SS / 64, KVD / 32, BB), dim3(32, 8), 0, s2>>>(Vtp, Vp);
    cudaEventRecord(eKV, s2);

    cudaStreamWaitEvent(0, eKV, 0);
    attn_f16<<<dim3(SS / 128, HQ, BB), 256, ATTN_SMEM_BYTES>>>(Qp, Kp, Vtp, out);
}